// round 2
// baseline (speedup 1.0000x reference)
#include <cuda_runtime.h>
#include <math.h>

// Problem shapes (fixed by the dataset; scratch sized for these)
#define MAXB 32
#define MAXP 24564
#define MAXO 32

// ---------------- scratch (device globals; no allocation allowed) -----------
__device__ float              d_btov[MAXB * MAXP];   // best truth overlap per prior
__device__ int                d_bti [MAXB * MAXP];   // best truth idx per prior
__device__ float              d_lc  [MAXB * MAXP];   // CE of negatives (0 for positives)
__device__ unsigned long long d_bp  [MAXB * MAXO];   // packed (iou_bits, ~p) best prior per truth
__device__ double             g_loss_l;
__device__ double             g_loss_c;
__device__ int                g_num_pos[MAXB];

// ---------------- init ------------------------------------------------------
__global__ void k_init(int B, int O) {
    int i = blockIdx.x * blockDim.x + threadIdx.x;
    if (i == 0) { g_loss_l = 0.0; g_loss_c = 0.0; }
    if (i < B) g_num_pos[i] = 0;
    if (i < B * O) d_bp[i] = 0ull;
}

// ---------------- matching: IoU, per-prior argmax, per-truth argmax ---------
__global__ __launch_bounds__(256) void k_match(
    const float* __restrict__ priors, const float* __restrict__ boxes,
    int B, int P, int O)
{
    int b = blockIdx.y;
    int p = blockIdx.x * blockDim.x + threadIdx.x;

    __shared__ float tb[MAXO * 4];
    __shared__ unsigned long long sbp[MAXO];
    if (threadIdx.x < O * 4) tb[threadIdx.x] = boxes[(size_t)b * O * 4 + threadIdx.x];
    if (threadIdx.x < O)     sbp[threadIdx.x] = 0ull;
    __syncthreads();

    if (p < P) {
        float4 pr = ((const float4*)priors)[p];
        // corner form exactly as reference (area from corners)
        float ax0 = pr.x - pr.z * 0.5f, ay0 = pr.y - pr.w * 0.5f;
        float ax1 = pr.x + pr.z * 0.5f, ay1 = pr.y + pr.w * 0.5f;
        float area_a = (ax1 - ax0) * (ay1 - ay0);

        float best = -1.0f; int bidx = 0;
        for (int o = 0; o < O; o++) {
            float bx0 = tb[o*4+0], by0 = tb[o*4+1], bx1 = tb[o*4+2], by1 = tb[o*4+3];
            float lx = fmaxf(ax0, bx0), ly = fmaxf(ay0, by0);
            float rx = fminf(ax1, bx1), ry = fminf(ay1, by1);
            float w = fmaxf(rx - lx, 0.0f), h = fmaxf(ry - ly, 0.0f);
            float inter = w * h;
            float area_b = (bx1 - bx0) * (by1 - by0);
            float iou = inter / (area_a + area_b - inter);
            if (iou > best) { best = iou; bidx = o; }  // first-max (JAX argmax)
            // per-truth best prior: max iou, tie -> smallest p
            unsigned long long key =
                (((unsigned long long)__float_as_uint(iou)) << 32) |
                (unsigned long long)(0xFFFFFFFFu - (unsigned)p);
            atomicMax(&sbp[o], key);
        }
        d_btov[(size_t)b * P + p] = best;
        d_bti [(size_t)b * P + p] = bidx;
    }
    __syncthreads();
    if (threadIdx.x < O && sbp[threadIdx.x] != 0ull)
        atomicMax(&d_bp[b * O + threadIdx.x], sbp[threadIdx.x]);
}

// ---------------- scatter: force each truth onto its best prior -------------
__global__ void k_scatter(int B, int P, int O) {
    int b = blockIdx.x * blockDim.x + threadIdx.x;
    if (b >= B) return;
    for (int o = 0; o < O; o++) {   // sequential -> last writer wins (torch loop)
        unsigned long long key = d_bp[b * O + o];
        int p = (int)(0xFFFFFFFFu - (unsigned)(key & 0xFFFFFFFFull));
        d_bti [(size_t)b * P + p] = o;
        d_btov[(size_t)b * P + p] = 2.0f;
    }
}

// ---------------- main loss: per-prior CE (warp/prior) + pos loc loss -------
__device__ __forceinline__ float sl1(float x) {
    float d = fabsf(x);
    return (d < 1.0f) ? 0.5f * d * d : d - 0.5f;
}

__global__ __launch_bounds__(256) void k_loss(
    const float* __restrict__ loc, const float* __restrict__ conf,
    const float* __restrict__ priors, const float* __restrict__ boxes,
    const int* __restrict__ labels, int B, int P, int O, int C)
{
    int b = blockIdx.y;
    int warp = threadIdx.x >> 5, lane = threadIdx.x & 31;
    int p = blockIdx.x * (blockDim.x >> 5) + warp;
    if (p >= P) return;

    const float* row = conf + ((size_t)b * P + p) * (size_t)C;
    float x0 = row[lane];
    float x1 = (lane + 32 < C) ? row[lane + 32] : -INFINITY;
    float x2 = (lane + 64 < C) ? row[lane + 64] : -INFINITY;

    float m = fmaxf(x0, fmaxf(x1, x2));
    #pragma unroll
    for (int off = 16; off; off >>= 1)
        m = fmaxf(m, __shfl_xor_sync(0xffffffffu, m, off));

    float s = expf(x0 - m) + expf(x1 - m) + expf(x2 - m); // exp(-inf)=0
    #pragma unroll
    for (int off = 16; off; off >>= 1)
        s += __shfl_xor_sync(0xffffffffu, s, off);

    if (lane == 0) {
        float lse = m + logf(s);
        size_t bp = (size_t)b * P + p;
        int   idx = d_bti[bp];
        float ov  = d_btov[bp];
        int   cls = (ov < 0.5f) ? 0 : labels[b * O + idx];
        float ce  = lse - row[cls];
        bool  pos = (cls > 0);
        d_lc[bp] = pos ? 0.0f : ce;
        if (pos) {
            atomicAdd(&g_loss_c, (double)ce);
            atomicAdd(&g_num_pos[b], 1);
            // encode + smooth L1 for this positive
            float4 t  = ((const float4*)boxes)[b * O + idx];
            float4 pr = ((const float4*)priors)[p];
            float gx = ((t.x + t.z) * 0.5f - pr.x) / (0.1f * pr.z);
            float gy = ((t.y + t.w) * 0.5f - pr.y) / (0.1f * pr.w);
            float gw = logf((t.z - t.x) / pr.z) / 0.2f;
            float gh = logf((t.w - t.y) / pr.w) / 0.2f;
            float4 lp = ((const float4*)loc)[bp];
            float l = sl1(lp.x - gx) + sl1(lp.y - gy) + sl1(lp.z - gw) + sl1(lp.w - gh);
            atomicAdd(&g_loss_l, (double)l);
        }
    }
}

// ---------------- hard-negative mining: radix-select top-K sum per batch ----
__global__ __launch_bounds__(1024) void k_mine(int B, int P) {
    int b = blockIdx.x;
    const float* lc = d_lc + (size_t)b * P;

    __shared__ unsigned int hist[256];
    __shared__ unsigned int s_prefix;
    __shared__ int s_remaining;
    __shared__ double sred[1024];

    int np = g_num_pos[b];
    long long K64 = 3LL * np;
    if (K64 > P - 1) K64 = P - 1;
    int K = (int)K64;
    if (K <= 0) return;

    if (threadIdx.x == 0) { s_prefix = 0u; s_remaining = K; }
    __syncthreads();

    for (int pass = 3; pass >= 0; pass--) {
        int shift = pass * 8;
        for (int i = threadIdx.x; i < 256; i += blockDim.x) hist[i] = 0u;
        __syncthreads();
        unsigned int prefix = s_prefix;
        for (int p = threadIdx.x; p < P; p += blockDim.x) {
            unsigned int key = __float_as_uint(lc[p]);  // all >= 0 -> monotone bits
            bool match = (pass == 3) || ((key >> (shift + 8)) == (prefix >> (shift + 8)));
            if (match) atomicAdd(&hist[(key >> shift) & 0xFF], 1u);
        }
        __syncthreads();
        if (threadIdx.x == 0) {
            int rem = s_remaining;
            unsigned int cum = 0; int dsel = 0;
            for (int d = 255; d >= 0; d--) {
                if (cum + hist[d] >= (unsigned)rem) { dsel = d; s_remaining = rem - (int)cum; break; }
                cum += hist[d];
            }
            s_prefix = prefix | ((unsigned)dsel << shift);
        }
        __syncthreads();
    }

    unsigned int tau = s_prefix;
    int remaining = s_remaining;  // # of tau-valued elements included in top-K
    double part = 0.0;
    for (int p = threadIdx.x; p < P; p += blockDim.x) {
        unsigned int key = __float_as_uint(lc[p]);
        if (key > tau) part += (double)lc[p];
    }
    sred[threadIdx.x] = part;
    __syncthreads();
    for (int s = 512; s; s >>= 1) {
        if (threadIdx.x < s) sred[threadIdx.x] += sred[threadIdx.x + s];
        __syncthreads();
    }
    if (threadIdx.x == 0) {
        double total = sred[0] + (double)remaining * (double)__uint_as_float(tau);
        atomicAdd(&g_loss_c, total);
    }
}

// ---------------- finalize ---------------------------------------------------
__global__ void k_final(float* out, int B) {
    double N = 0.0;
    for (int b = 0; b < B; b++) N += (double)g_num_pos[b];
    float Nf = (float)N;
    out[0] = (float)g_loss_l / Nf + (float)g_loss_c / Nf;
}

// ---------------- launch ------------------------------------------------------
extern "C" void kernel_launch(void* const* d_in, const int* in_sizes, int n_in,
                              void* d_out, int out_size)
{
    const float* loc    = (const float*)d_in[0];
    const float* conf   = (const float*)d_in[1];
    const float* priors = (const float*)d_in[2];
    const float* boxes  = (const float*)d_in[3];
    const int*   labels = (const int*)  d_in[4];

    int P = in_sizes[2] / 4;
    int B = in_sizes[0] / (P * 4);
    int C = (int)((long long)in_sizes[1] / ((long long)B * P));
    int O = in_sizes[4] / B;

    k_init<<<1, 1024>>>(B, O);

    dim3 g1((P + 255) / 256, B);
    k_match<<<g1, 256>>>(priors, boxes, B, P, O);

    k_scatter<<<1, 32>>>(B, P, O);

    dim3 g3((P + 7) / 8, B);   // 8 warps/block, warp per prior
    k_loss<<<g3, 256>>>(loc, conf, priors, boxes, labels, B, P, O, C);

    k_mine<<<B, 1024>>>(B, P);

    k_final<<<1, 1>>>((float*)d_out, B);
}

// round 3
// speedup vs baseline: 1.2080x; 1.2080x over previous
#include <cuda_runtime.h>
#include <math.h>

#define MAXB 32
#define MAXP 24564
#define MAXO 32
#define LTILE 128   // priors per block in k_loss

// ---------------- scratch ----------------------------------------------------
__device__ float              d_btov[MAXB * MAXP];
__device__ int                d_bti [MAXB * MAXP];
__device__ float              d_lc  [MAXB * MAXP];
__device__ unsigned long long d_bp  [MAXB * MAXO];
__device__ double             g_loss_l;
__device__ double             g_loss_c;
__device__ int                g_num_pos[MAXB];

// ---------------- init --------------------------------------------------------
__global__ void k_init(int B, int O) {
    int i = blockIdx.x * blockDim.x + threadIdx.x;
    if (i == 0) { g_loss_l = 0.0; g_loss_c = 0.0; }
    if (i < B) g_num_pos[i] = 0;
    if (i < B * O) d_bp[i] = 0ull;
}

// ---------------- matching ----------------------------------------------------
__global__ __launch_bounds__(256) void k_match(
    const float* __restrict__ priors, const float* __restrict__ boxes,
    int B, int P, int O)
{
    int b = blockIdx.y;
    int p = blockIdx.x * blockDim.x + threadIdx.x;
    bool valid = (p < P);
    int  pc = valid ? p : (P - 1);

    __shared__ float tb[MAXO * 4];
    __shared__ unsigned long long sbp[MAXO];
    if (threadIdx.x < O * 4) tb[threadIdx.x] = boxes[(size_t)b * O * 4 + threadIdx.x];
    if (threadIdx.x < O)     sbp[threadIdx.x] = 0ull;
    __syncthreads();

    float4 pr = ((const float4*)priors)[pc];
    float ax0 = pr.x - pr.z * 0.5f, ay0 = pr.y - pr.w * 0.5f;
    float ax1 = pr.x + pr.z * 0.5f, ay1 = pr.y + pr.w * 0.5f;
    float area_a = (ax1 - ax0) * (ay1 - ay0);

    float best = -1.0f; int bidx = 0;
    for (int o = 0; o < O; o++) {
        float bx0 = tb[o*4+0], by0 = tb[o*4+1], bx1 = tb[o*4+2], by1 = tb[o*4+3];
        float lx = fmaxf(ax0, bx0), ly = fmaxf(ay0, by0);
        float rx = fminf(ax1, bx1), ry = fminf(ay1, by1);
        float w = fmaxf(rx - lx, 0.0f), h = fmaxf(ry - ly, 0.0f);
        float inter = w * h;
        float area_b = (bx1 - bx0) * (by1 - by0);
        float iou = inter / (area_a + area_b - inter);
        if (valid && iou > best) { best = iou; bidx = o; }
        // per-truth best prior: prune with warp REDUX, atomic only from the max lane(s)
        unsigned int kb = valid ? __float_as_uint(iou) : 0u;   // iou >= 0 -> monotone
        unsigned int wmax = __reduce_max_sync(0xffffffffu, kb);
        if (valid && kb == wmax) {
            unsigned long long key =
                (((unsigned long long)kb) << 32) |
                (unsigned long long)(0xFFFFFFFFu - (unsigned)p);
            atomicMax(&sbp[o], key);
        }
    }
    if (valid) {
        d_btov[(size_t)b * P + p] = best;
        d_bti [(size_t)b * P + p] = bidx;
    }
    __syncthreads();
    if (threadIdx.x < O && sbp[threadIdx.x] != 0ull)
        atomicMax(&d_bp[b * O + threadIdx.x], sbp[threadIdx.x]);
}

// ---------------- scatter: force each truth onto its best prior ----------------
__global__ void k_scatter(int B, int P, int O) {
    int b = blockIdx.x * blockDim.x + threadIdx.x;
    if (b >= B) return;
    for (int o = 0; o < O; o++) {   // sequential -> last writer wins
        unsigned long long key = d_bp[b * O + o];
        int p = (int)(0xFFFFFFFFu - (unsigned)(key & 0xFFFFFFFFull));
        d_bti [(size_t)b * P + p] = o;
        d_btov[(size_t)b * P + p] = 2.0f;
    }
}

// ---------------- main loss: smem-staged, thread-per-prior ---------------------
__device__ __forceinline__ float sl1(float x) {
    float d = fabsf(x);
    return (d < 1.0f) ? 0.5f * d * d : d - 0.5f;
}

__global__ __launch_bounds__(LTILE) void k_loss(
    const float* __restrict__ loc, const float* __restrict__ conf,
    const float* __restrict__ priors, const float* __restrict__ boxes,
    const int* __restrict__ labels, int B, int P, int O, int C)
{
    extern __shared__ float sh[];   // LTILE * C floats
    int b  = blockIdx.y;
    int p0 = blockIdx.x * LTILE;
    int nrow = min(LTILE, P - p0);
    int nflt = nrow * C;

    const float* base = conf + ((size_t)b * P + p0) * (size_t)C;
    int nv4 = nflt >> 2;
    const float4* g4 = (const float4*)base;   // base is 16B aligned: p0*C*4 % 16 == 0 for C=81,p0%4==0
    float4* s4 = (float4*)sh;
    for (int i = threadIdx.x; i < nv4; i += LTILE) s4[i] = g4[i];
    for (int i = (nv4 << 2) + threadIdx.x; i < nflt; i += LTILE) sh[i] = base[i];
    __syncthreads();

    int t = threadIdx.x;
    if (t >= nrow) return;
    int p = p0 + t;
    const float* row = sh + t * C;

    float s0 = 0.f, s1 = 0.f, s2 = 0.f, s3 = 0.f;
    int c = 0;
    for (; c + 3 < C; c += 4) {
        s0 += __expf(row[c]);
        s1 += __expf(row[c+1]);
        s2 += __expf(row[c+2]);
        s3 += __expf(row[c+3]);
    }
    for (; c < C; c++) s0 += __expf(row[c]);
    float lse = __logf((s0 + s1) + (s2 + s3));

    size_t bp = (size_t)b * P + p;
    int   idx = d_bti[bp];
    float ov  = d_btov[bp];
    int   cls = (ov < 0.5f) ? 0 : labels[b * O + idx];
    float ce  = lse - row[cls];
    bool  pos = (cls > 0);
    d_lc[bp] = pos ? 0.0f : ce;
    if (pos) {
        atomicAdd(&g_loss_c, (double)ce);
        atomicAdd(&g_num_pos[b], 1);
        float4 tr = ((const float4*)boxes)[b * O + idx];
        float4 pv = ((const float4*)priors)[p];
        float gx = ((tr.x + tr.z) * 0.5f - pv.x) / (0.1f * pv.z);
        float gy = ((tr.y + tr.w) * 0.5f - pv.y) / (0.1f * pv.w);
        float gw = logf((tr.z - tr.x) / pv.z) / 0.2f;
        float gh = logf((tr.w - tr.y) / pv.w) / 0.2f;
        float4 lp = ((const float4*)loc)[bp];
        float l = sl1(lp.x - gx) + sl1(lp.y - gy) + sl1(lp.z - gw) + sl1(lp.w - gh);
        atomicAdd(&g_loss_l, (double)l);
    }
}

// ---------------- hard-negative mining: radix-select top-K sum -----------------
__global__ __launch_bounds__(1024) void k_mine(int B, int P) {
    int b = blockIdx.x;
    const float* lc = d_lc + (size_t)b * P;

    __shared__ unsigned int hist[256];
    __shared__ unsigned int s_prefix;
    __shared__ int s_remaining;
    __shared__ double sred[1024];

    int np = g_num_pos[b];
    long long K64 = 3LL * np;
    if (K64 > P - 1) K64 = P - 1;
    int K = (int)K64;
    if (K <= 0) return;

    if (threadIdx.x == 0) { s_prefix = 0u; s_remaining = K; }
    __syncthreads();

    int iters = (P + blockDim.x - 1) / blockDim.x;
    int lane = threadIdx.x & 31;

    for (int pass = 3; pass >= 0; pass--) {
        int shift = pass * 8;
        for (int i = threadIdx.x; i < 256; i += blockDim.x) hist[i] = 0u;
        __syncthreads();
        unsigned int prefix = s_prefix;
        for (int it = 0; it < iters; it++) {
            int p = it * blockDim.x + threadIdx.x;
            bool inb = (p < P);
            unsigned int key = inb ? __float_as_uint(lc[p]) : 0u;
            bool match = inb &&
                ((pass == 3) || ((key >> (shift + 8)) == (prefix >> (shift + 8))));
            unsigned int active = __ballot_sync(0xffffffffu, match);
            if (match) {
                unsigned int bin = (key >> shift) & 0xFF;
                unsigned int same = __match_any_sync(active, bin);
                int leader = __ffs(same) - 1;
                if (lane == leader) atomicAdd(&hist[bin], __popc(same));
            }
        }
        __syncthreads();
        if (threadIdx.x == 0) {
            int rem = s_remaining;
            unsigned int cum = 0; int dsel = 0;
            for (int d = 255; d >= 0; d--) {
                if (cum + hist[d] >= (unsigned)rem) { dsel = d; s_remaining = rem - (int)cum; break; }
                cum += hist[d];
            }
            s_prefix = prefix | ((unsigned)dsel << shift);
        }
        __syncthreads();
    }

    unsigned int tau = s_prefix;
    int remaining = s_remaining;
    double part = 0.0;
    for (int p = threadIdx.x; p < P; p += blockDim.x) {
        unsigned int key = __float_as_uint(lc[p]);
        if (key > tau) part += (double)lc[p];
    }
    sred[threadIdx.x] = part;
    __syncthreads();
    for (int s = 512; s; s >>= 1) {
        if (threadIdx.x < s) sred[threadIdx.x] += sred[threadIdx.x + s];
        __syncthreads();
    }
    if (threadIdx.x == 0) {
        double total = sred[0] + (double)remaining * (double)__uint_as_float(tau);
        atomicAdd(&g_loss_c, total);
    }
}

// ---------------- finalize -----------------------------------------------------
__global__ void k_final(float* out, int B) {
    double N = 0.0;
    for (int b = 0; b < B; b++) N += (double)g_num_pos[b];
    float Nf = (float)N;
    out[0] = (float)g_loss_l / Nf + (float)g_loss_c / Nf;
}

// ---------------- launch ---------------------------------------------------------
extern "C" void kernel_launch(void* const* d_in, const int* in_sizes, int n_in,
                              void* d_out, int out_size)
{
    const float* loc    = (const float*)d_in[0];
    const float* conf   = (const float*)d_in[1];
    const float* priors = (const float*)d_in[2];
    const float* boxes  = (const float*)d_in[3];
    const int*   labels = (const int*)  d_in[4];

    int P = in_sizes[2] / 4;
    int B = in_sizes[0] / (P * 4);
    int C = (int)((long long)in_sizes[1] / ((long long)B * P));
    int O = in_sizes[4] / B;

    k_init<<<1, 1024>>>(B, O);

    dim3 g1((P + 255) / 256, B);
    k_match<<<g1, 256>>>(priors, boxes, B, P, O);

    k_scatter<<<1, 32>>>(B, P, O);

    dim3 g3((P + LTILE - 1) / LTILE, B);
    size_t smem = (size_t)LTILE * C * sizeof(float);
    k_loss<<<g3, LTILE, smem>>>(loc, conf, priors, boxes, labels, B, P, O, C);

    k_mine<<<B, 1024>>>(B, P);

    k_final<<<1, 1>>>((float*)d_out, B);
}